// round 12
// baseline (speedup 1.0000x reference)
#include <cuda_runtime.h>
#include <cuda_fp16.h>
#include <cstdint>

#define N_NODES 100000
#define N_EDGES 1600000
#define HID 128
#define NCLS 47
#define NBLK 391                                  // ceil(N_NODES/256)

// ---------------- scratch (static device globals; no runtime allocation) ----
__device__ __half g_yh[(size_t)N_NODES * HID];   // GEMM output fp16 (gather source)
__device__ __half g_hh[(size_t)N_NODES * HID];   // post-activation hidden fp16
__device__ __half g_wt0[HID * HID];              // W0^T fp16  [n][k]
__device__ __half g_wt1[HID * HID];              // W1^T fp16  [n][k]
__device__ __half g_wtc[64 * HID];               // Wc^T fp16  [n][k], rows 47..63 = 0
__device__ float  g_cs[N_NODES];
__device__ float  g_cd[N_NODES];
__device__ int    g_outdeg[N_NODES];
__device__ int    g_indeg [N_NODES];
__device__ int    g_cursor[N_NODES];
__device__ int    g_rowstart[N_NODES + 1];
__device__ int    g_csrc[N_EDGES];
__device__ int    g_bsum[NBLK];
__device__ int    g_boff[NBLK];

// ---- fused init: zero counters + W pre-transpose/convert ------------------
__global__ void __launch_bounds__(256) init_kernel(const float* __restrict__ W0,
                                                   const float* __restrict__ W1,
                                                   const float* __restrict__ Wc) {
    int i = blockIdx.x * 256 + threadIdx.x;
    if (i < N_NODES) { g_outdeg[i] = 0; g_indeg[i] = 0; g_cursor[i] = 0; }
    if (i < HID * HID) {
        int n = i >> 7, k = i & 127;
        g_wt0[i] = __float2half_rn(W0[k * 128 + n]);
        g_wt1[i] = __float2half_rn(W1[k * 128 + n]);
    }
    if (i < 64 * HID) {
        int n = i >> 7, k = i & 127;
        g_wtc[i] = (n < NCLS) ? __float2half_rn(Wc[k * NCLS + n])
                              : __float2half_rn(0.f);
    }
}

__global__ void degree_kernel(const int* __restrict__ edges) {
    int i = blockIdx.x * blockDim.x + threadIdx.x;
    if (i < N_EDGES) {
        atomicAdd(&g_outdeg[edges[i]], 1);
        atomicAdd(&g_indeg [edges[N_EDGES + i]], 1);
    }
}

// ---- fused: finish degrees (cs/cd) + per-block indeg sums -----------------
__global__ void __launch_bounds__(256) finish_deg_bsum_kernel() {
    __shared__ int sm[8];
    int i = blockIdx.x * 256 + threadIdx.x;
    int v = 0;
    if (i < N_NODES) {
        int od = g_outdeg[i];
        v = g_indeg[i];
        g_cs[i] = rsqrtf(fmaxf((float)od, 1.f));
        g_cd[i] = rsqrtf(fmaxf((float)v,  1.f));
    }
    int s = v;
#pragma unroll
    for (int off = 16; off > 0; off >>= 1)
        s += __shfl_down_sync(0xffffffffu, s, off);
    if ((threadIdx.x & 31) == 0) sm[threadIdx.x >> 5] = s;
    __syncthreads();
    if (threadIdx.x < 8) {
        int t = sm[threadIdx.x];
#pragma unroll
        for (int off = 4; off > 0; off >>= 1)
            t += __shfl_down_sync(0xffu, t, off);
        if (threadIdx.x == 0) g_bsum[blockIdx.x] = t;
    }
}

// ---- scan phase 2 ----------------------------------------------------------
__global__ void __launch_bounds__(512) scan_bsum_kernel() {
    __shared__ int part[512];
    int t = threadIdx.x;
    part[t] = (t < NBLK) ? g_bsum[t] : 0;
    __syncthreads();
    for (int off = 1; off < 512; off <<= 1) {
        int v = (t >= off) ? part[t - off] : 0;
        __syncthreads();
        part[t] += v;
        __syncthreads();
    }
    if (t < NBLK) g_boff[t] = (t == 0) ? 0 : part[t - 1];
    if (t == 0) g_rowstart[N_NODES] = N_EDGES;
}

// ---- scan phase 3 ----------------------------------------------------------
__global__ void __launch_bounds__(256) rowstart_kernel() {
    __shared__ int part[256];
    int t = threadIdx.x;
    int i = blockIdx.x * 256 + t;
    int v = (i < N_NODES) ? g_indeg[i] : 0;
    part[t] = v;
    __syncthreads();
    for (int off = 1; off < 256; off <<= 1) {
        int u = (t >= off) ? part[t - off] : 0;
        __syncthreads();
        part[t] += u;
        __syncthreads();
    }
    if (i < N_NODES)
        g_rowstart[i] = g_boff[blockIdx.x] + part[t] - v;
}

__global__ void fill_csr_kernel(const int* __restrict__ edges) {
    int i = blockIdx.x * blockDim.x + threadIdx.x;
    if (i < N_EDGES) {
        int s = edges[i];
        int d = edges[N_EDGES + i];
        int pos = g_rowstart[d] + atomicAdd(&g_cursor[d], 1);
        g_csrc[pos] = s;
    }
}

// ---------------- tensor-core GEMM: Yh = fp16((A*c_src) @ W) ---------------
// Block 64x128, two 64-K chunks, software-pipelined. 8 warps (2x4),
// warp tile 32x32, m16n8k16.
__global__ void __launch_bounds__(256) gemm_mma_kernel(
    const float* __restrict__ X, int layer, int M)
{
    __shared__ __align__(16) __half Ah[64][72];
    __shared__ __align__(16) __half Bt[128][72];

    const __half* Wt = layer ? g_wt1 : g_wt0;

    int tid  = threadIdx.x;
    int lane = tid & 31;
    int warp = tid >> 5;
    int wm   = warp >> 2;
    int wn   = warp & 3;
    int g    = lane >> 2;
    int tq   = lane & 3;
    int row0 = blockIdx.x * 64;

    uint32_t ahBase = (uint32_t)__cvta_generic_to_shared(&Ah[0][0]);
    uint32_t btBase = (uint32_t)__cvta_generic_to_shared(&Bt[0][0]);
    int atrow = lane & 15;
    int athalf = (lane >> 4) * 8;
    uint32_t aAddr[2];
#pragma unroll
    for (int ma = 0; ma < 2; ma++)
        aAddr[ma] = ahBase + ((wm * 32 + ma * 16 + atrow) * 72 + athalf) * 2;
    int btrow = (lane & 7) + ((lane >> 4) << 3);
    int bthalf = ((lane >> 3) & 1) * 8;
    uint32_t bAddr[2];
#pragma unroll
    for (int p = 0; p < 2; p++)
        bAddr[p] = btBase + ((wn * 32 + p * 16 + btrow) * 72 + bthalf) * 2;

    int ar[2], akb[2];
#pragma unroll
    for (int t = 0; t < 2; t++) {
        int id = tid + t * 256;
        ar[t]  = id >> 3;
        akb[t] = (id & 7) * 8;
    }
    int bn[4], bkb[4];
#pragma unroll
    for (int t = 0; t < 4; t++) {
        int id = tid + t * 256;
        bn[t]  = id >> 3;
        bkb[t] = (id & 7) * 8;
    }

    float acc[2][4][4];
#pragma unroll
    for (int ma = 0; ma < 2; ma++)
#pragma unroll
        for (int na = 0; na < 4; na++)
#pragma unroll
            for (int q = 0; q < 4; q++) acc[ma][na][q] = 0.f;

    uint4 ast[2], bst[4];

    // ---- load chunk 0 ----
#pragma unroll
    for (int t = 0; t < 2; t++) {
        int grow = row0 + ar[t];
        __half2 h[4];
        if (grow < M) {
            float s = g_cs[grow];
            if (!layer) {
                const float4* p = (const float4*)(X + (size_t)grow * 128 + akb[t]);
                float4 v0 = p[0], v1 = p[1];
                h[0] = __floats2half2_rn(v0.x * s, v0.y * s);
                h[1] = __floats2half2_rn(v0.z * s, v0.w * s);
                h[2] = __floats2half2_rn(v1.x * s, v1.y * s);
                h[3] = __floats2half2_rn(v1.z * s, v1.w * s);
            } else {
                uint4 u = *(const uint4*)(g_hh + (size_t)grow * 128 + akb[t]);
                const __half2* hp = (const __half2*)&u;
#pragma unroll
                for (int q = 0; q < 4; q++) {
                    float2 f = __half22float2(hp[q]);
                    h[q] = __floats2half2_rn(f.x * s, f.y * s);
                }
            }
        } else {
            __half2 z = __floats2half2_rn(0.f, 0.f);
            h[0] = z; h[1] = z; h[2] = z; h[3] = z;
        }
        ast[t].x = *(uint32_t*)&h[0]; ast[t].y = *(uint32_t*)&h[1];
        ast[t].z = *(uint32_t*)&h[2]; ast[t].w = *(uint32_t*)&h[3];
    }
#pragma unroll
    for (int t = 0; t < 4; t++)
        bst[t] = *(const uint4*)(Wt + (size_t)bn[t] * 128 + bkb[t]);

#pragma unroll
    for (int t = 0; t < 2; t++) *(uint4*)&Ah[ar[t]][akb[t]] = ast[t];
#pragma unroll
    for (int t = 0; t < 4; t++) *(uint4*)&Bt[bn[t]][bkb[t]] = bst[t];
    __syncthreads();

    // ---- prefetch chunk 1 into registers ----
#pragma unroll
    for (int t = 0; t < 2; t++) {
        int grow = row0 + ar[t];
        __half2 h[4];
        if (grow < M) {
            float s = g_cs[grow];
            if (!layer) {
                const float4* p = (const float4*)(X + (size_t)grow * 128 + 64 + akb[t]);
                float4 v0 = p[0], v1 = p[1];
                h[0] = __floats2half2_rn(v0.x * s, v0.y * s);
                h[1] = __floats2half2_rn(v0.z * s, v0.w * s);
                h[2] = __floats2half2_rn(v1.x * s, v1.y * s);
                h[3] = __floats2half2_rn(v1.z * s, v1.w * s);
            } else {
                uint4 u = *(const uint4*)(g_hh + (size_t)grow * 128 + 64 + akb[t]);
                const __half2* hp = (const __half2*)&u;
#pragma unroll
                for (int q = 0; q < 4; q++) {
                    float2 f = __half22float2(hp[q]);
                    h[q] = __floats2half2_rn(f.x * s, f.y * s);
                }
            }
        } else {
            __half2 z = __floats2half2_rn(0.f, 0.f);
            h[0] = z; h[1] = z; h[2] = z; h[3] = z;
        }
        ast[t].x = *(uint32_t*)&h[0]; ast[t].y = *(uint32_t*)&h[1];
        ast[t].z = *(uint32_t*)&h[2]; ast[t].w = *(uint32_t*)&h[3];
    }
#pragma unroll
    for (int t = 0; t < 4; t++)
        bst[t] = *(const uint4*)(Wt + (size_t)bn[t] * 128 + 64 + bkb[t]);

    // ---- MMA chunk 0 / store chunk 1 / MMA chunk 1 ----
#pragma unroll
    for (int chunk = 0; chunk < 2; chunk++) {
#pragma unroll
        for (int ks = 0; ks < 64; ks += 16) {
            uint32_t a[2][4], b[4][2];
#pragma unroll
            for (int ma = 0; ma < 2; ma++) {
                asm volatile(
                    "ldmatrix.sync.aligned.m8n8.x4.shared.b16 {%0,%1,%2,%3}, [%4];\n"
                    : "=r"(a[ma][0]), "=r"(a[ma][1]), "=r"(a[ma][2]), "=r"(a[ma][3])
                    : "r"(aAddr[ma] + ks * 2));
            }
#pragma unroll
            for (int p = 0; p < 2; p++) {
                uint32_t r0, r1, r2, r3;
                asm volatile(
                    "ldmatrix.sync.aligned.m8n8.x4.shared.b16 {%0,%1,%2,%3}, [%4];\n"
                    : "=r"(r0), "=r"(r1), "=r"(r2), "=r"(r3)
                    : "r"(bAddr[p] + ks * 2));
                b[p * 2 + 0][0] = r0; b[p * 2 + 0][1] = r1;
                b[p * 2 + 1][0] = r2; b[p * 2 + 1][1] = r3;
            }
#pragma unroll
            for (int ma = 0; ma < 2; ma++)
#pragma unroll
                for (int na = 0; na < 4; na++) {
                    asm volatile(
                        "mma.sync.aligned.m16n8k16.row.col.f32.f16.f16.f32 "
                        "{%0,%1,%2,%3}, {%4,%5,%6,%7}, {%8,%9}, {%0,%1,%2,%3};\n"
                        : "+f"(acc[ma][na][0]), "+f"(acc[ma][na][1]),
                          "+f"(acc[ma][na][2]), "+f"(acc[ma][na][3])
                        : "r"(a[ma][0]), "r"(a[ma][1]), "r"(a[ma][2]), "r"(a[ma][3]),
                          "r"(b[na][0]), "r"(b[na][1]));
                }
        }
        if (chunk == 0) {
            __syncthreads();
#pragma unroll
            for (int t = 0; t < 2; t++) *(uint4*)&Ah[ar[t]][akb[t]] = ast[t];
#pragma unroll
            for (int t = 0; t < 4; t++) *(uint4*)&Bt[bn[t]][bkb[t]] = bst[t];
            __syncthreads();
        }
    }

    // ---- epilogue: fp32 acc -> fp16 g_yh ----
#pragma unroll
    for (int ma = 0; ma < 2; ma++) {
        int r0 = row0 + wm * 32 + ma * 16 + g;
        int r1 = r0 + 8;
#pragma unroll
        for (int na = 0; na < 4; na++) {
            int col = wn * 32 + na * 8 + tq * 2;
            if (r0 < M)
                *(__half2*)(g_yh + (size_t)r0 * 128 + col) =
                    __floats2half2_rn(acc[ma][na][0], acc[ma][na][1]);
            if (r1 < M)
                *(__half2*)(g_yh + (size_t)r1 * 128 + col) =
                    __floats2half2_rn(acc[ma][na][2], acc[ma][na][3]);
        }
    }
}

// ---------------- CSR gather: LDG.128, 2 source rows per warp-instruction ---
// warp per dst node. Half-warps split source pairs: lanes 0-15 read row
// s_{2j}, lanes 16-31 read s_{2j+1}; each lane loads uint4 (8 halves = 16B).
// Partials combined at the end via shfl_xor(16). Halves LSU-issue count.
__global__ void __launch_bounds__(256) gather_kernel(const float* __restrict__ b) {
    int w    = blockIdx.x * 8 + (threadIdx.x >> 5);
    int lane = threadIdx.x & 31;
    if (w >= N_NODES) return;

    int beg = __ldg(&g_rowstart[w]);
    int end = __ldg(&g_rowstart[w + 1]);

    int col8 = (lane & 15) * 8;     // feature offset (halves)
    int sh   = lane >> 4;           // which source of the pair

    float acc[8];
#pragma unroll
    for (int q = 0; q < 8; q++) acc[q] = 0.f;

    for (int base = beg; base < end; base += 32) {
        int n   = end - base;
        int m   = n < 32 ? n : 32;
        int idx = (lane < m) ? __ldg(&g_csrc[base + lane]) : 0;

        int j = 0;
        for (; j + 8 <= m; j += 8) {          // 4 pairs = 8 sources, 4 LDG.128
            uint4 v[4];
#pragma unroll
            for (int p = 0; p < 4; p++) {
                int s = __shfl_sync(0xffffffffu, idx, j + p * 2 + sh);
                v[p] = *(const uint4*)(g_yh + (size_t)s * 128 + col8);
            }
#pragma unroll
            for (int p = 0; p < 4; p++) {
                const __half2* hp = (const __half2*)&v[p];
#pragma unroll
                for (int q = 0; q < 4; q++) {
                    float2 f = __half22float2(hp[q]);
                    acc[q * 2 + 0] += f.x;
                    acc[q * 2 + 1] += f.y;
                }
            }
        }
        for (; j + 2 <= m; j += 2) {          // remaining pairs
            int s = __shfl_sync(0xffffffffu, idx, j + sh);
            uint4 v = *(const uint4*)(g_yh + (size_t)s * 128 + col8);
            const __half2* hp = (const __half2*)&v;
#pragma unroll
            for (int q = 0; q < 4; q++) {
                float2 f = __half22float2(hp[q]);
                acc[q * 2 + 0] += f.x;
                acc[q * 2 + 1] += f.y;
            }
        }
        if (j < m) {                           // odd tail: lower half only
            int s = __shfl_sync(0xffffffffu, idx, j);
            if (sh == 0) {
                uint4 v = *(const uint4*)(g_yh + (size_t)s * 128 + col8);
                const __half2* hp = (const __half2*)&v;
#pragma unroll
                for (int q = 0; q < 4; q++) {
                    float2 f = __half22float2(hp[q]);
                    acc[q * 2 + 0] += f.x;
                    acc[q * 2 + 1] += f.y;
                }
            }
        }
    }

    // combine the two half-warp partials (same feature cols)
#pragma unroll
    for (int q = 0; q < 8; q++)
        acc[q] += __shfl_xor_sync(0xffffffffu, acc[q], 16);

    if (sh == 0) {
        float c = g_cd[w];
        float4 bb0 = *(const float4*)(b + col8);
        float4 bb1 = *(const float4*)(b + col8 + 4);
        __half2 o[4];
        o[0] = __floats2half2_rn(fmaxf(fmaf(acc[0], c, bb0.x), 0.f),
                                 fmaxf(fmaf(acc[1], c, bb0.y), 0.f));
        o[1] = __floats2half2_rn(fmaxf(fmaf(acc[2], c, bb0.z), 0.f),
                                 fmaxf(fmaf(acc[3], c, bb0.w), 0.f));
        o[2] = __floats2half2_rn(fmaxf(fmaf(acc[4], c, bb1.x), 0.f),
                                 fmaxf(fmaf(acc[5], c, bb1.y), 0.f));
        o[3] = __floats2half2_rn(fmaxf(fmaf(acc[6], c, bb1.z), 0.f),
                                 fmaxf(fmaf(acc[7], c, bb1.w), 0.f));
        uint4 pack;
        pack.x = *(uint32_t*)&o[0]; pack.y = *(uint32_t*)&o[1];
        pack.z = *(uint32_t*)&o[2]; pack.w = *(uint32_t*)&o[3];
        *(uint4*)(g_hh + (size_t)w * 128 + col8) = pack;
    }
}

// ---------------- classifier (tensor core): out = g_hh @ Wc + bc -----------
__global__ void __launch_bounds__(256) cls_mma_kernel(
    const float* __restrict__ bc, float* __restrict__ out, int M)
{
    __shared__ __align__(16) __half Ah[64][136];
    __shared__ __align__(16) __half Bt[64][136];

    int tid  = threadIdx.x;
    int lane = tid & 31;
    int warp = tid >> 5;
    int wm   = warp >> 2;
    int wn   = warp & 3;
    int g    = lane >> 2;
    int tq   = lane & 3;
    int row0 = blockIdx.x * 64;

#pragma unroll
    for (int t = 0; t < 4; t++) {
        int id = tid + t * 256;
        int r  = id >> 4;
        int kb = (id & 15) * 8;
        int grow = row0 + r;
        uint4 v = make_uint4(0u, 0u, 0u, 0u);
        if (grow < M) v = *(const uint4*)(g_hh + (size_t)grow * 128 + kb);
        *(uint4*)&Ah[r][kb] = v;
    }
#pragma unroll
    for (int t = 0; t < 4; t++) {
        int id = tid + t * 256;
        int n  = id >> 4;
        int kb = (id & 15) * 8;
        *(uint4*)&Bt[n][kb] = *(const uint4*)(g_wtc + (size_t)n * 128 + kb);
    }
    __syncthreads();

    uint32_t ahBase = (uint32_t)__cvta_generic_to_shared(&Ah[0][0]);
    uint32_t btBase = (uint32_t)__cvta_generic_to_shared(&Bt[0][0]);
    int atrow = lane & 15;
    int athalf = (lane >> 4) * 8;
    uint32_t aAddr[2];
#pragma unroll
    for (int ma = 0; ma < 2; ma++)
        aAddr[ma] = ahBase + ((wm * 32 + ma * 16 + atrow) * 136 + athalf) * 2;
    int btrow = (lane & 7) + ((lane >> 4) << 3);
    int bthalf = ((lane >> 3) & 1) * 8;
    uint32_t bAddr = btBase + ((wn * 16 + btrow) * 136 + bthalf) * 2;

    float acc[2][2][4];
#pragma unroll
    for (int ma = 0; ma < 2; ma++)
#pragma unroll
        for (int na = 0; na < 2; na++)
#pragma unroll
            for (int q = 0; q < 4; q++) acc[ma][na][q] = 0.f;

#pragma unroll
    for (int ks = 0; ks < 128; ks += 16) {
        uint32_t a[2][4], b[2][2];
#pragma unroll
        for (int ma = 0; ma < 2; ma++) {
            asm volatile(
                "ldmatrix.sync.aligned.m8n8.x4.shared.b16 {%0,%1,%2,%3}, [%4];\n"
                : "=r"(a[ma][0]), "=r"(a[ma][1]), "=r"(a[ma][2]), "=r"(a[ma][3])
                : "r"(aAddr[ma] + ks * 2));
        }
        {
            uint32_t r0, r1, r2, r3;
            asm volatile(
                "ldmatrix.sync.aligned.m8n8.x4.shared.b16 {%0,%1,%2,%3}, [%4];\n"
                : "=r"(r0), "=r"(r1), "=r"(r2), "=r"(r3)
                : "r"(bAddr + ks * 2));
            b[0][0] = r0; b[0][1] = r1;
            b[1][0] = r2; b[1][1] = r3;
        }
#pragma unroll
        for (int ma = 0; ma < 2; ma++)
#pragma unroll
            for (int na = 0; na < 2; na++) {
                asm volatile(
                    "mma.sync.aligned.m16n8k16.row.col.f32.f16.f16.f32 "
                    "{%0,%1,%2,%3}, {%4,%5,%6,%7}, {%8,%9}, {%0,%1,%2,%3};\n"
                    : "+f"(acc[ma][na][0]), "+f"(acc[ma][na][1]),
                      "+f"(acc[ma][na][2]), "+f"(acc[ma][na][3])
                    : "r"(a[ma][0]), "r"(a[ma][1]), "r"(a[ma][2]), "r"(a[ma][3]),
                      "r"(b[na][0]), "r"(b[na][1]));
            }
    }

#pragma unroll
    for (int ma = 0; ma < 2; ma++) {
        int r0 = row0 + wm * 32 + ma * 16 + g;
        int r1 = r0 + 8;
#pragma unroll
        for (int na = 0; na < 2; na++) {
            int col = wn * 16 + na * 8 + tq * 2;
            float bb0 = (col < NCLS)     ? bc[col]     : 0.f;
            float bb1 = (col + 1 < NCLS) ? bc[col + 1] : 0.f;
            if (r0 < M) {
                if (col < NCLS)     out[(size_t)r0 * NCLS + col]     = acc[ma][na][0] + bb0;
                if (col + 1 < NCLS) out[(size_t)r0 * NCLS + col + 1] = acc[ma][na][1] + bb1;
            }
            if (r1 < M) {
                if (col < NCLS)     out[(size_t)r1 * NCLS + col]     = acc[ma][na][2] + bb0;
                if (col + 1 < NCLS) out[(size_t)r1 * NCLS + col + 1] = acc[ma][na][3] + bb1;
            }
        }
    }
}

// ---------------- launch ----------------------------------------------------
extern "C" void kernel_launch(void* const* d_in, const int* in_sizes, int n_in,
                              void* d_out, int out_size)
{
    const float* x     = (const float*)d_in[0];
    const int*   edges = (const int*)  d_in[1];
    const float* W0    = (const float*)d_in[2];
    const float* b0    = (const float*)d_in[3];
    const float* W1    = (const float*)d_in[4];
    const float* b1    = (const float*)d_in[5];
    const float* Wc    = (const float*)d_in[6];
    const float* bc    = (const float*)d_in[7];
    float* out = (float*)d_out;

    const int nodeBlocks   = (N_NODES + 255) / 256;      // 391
    const int edgeBlocks   = (N_EDGES + 255) / 256;      // 6250
    const int gemmBlocks   = (N_NODES + 63) / 64;        // 1563
    const int gatherBlocks = (N_NODES + 7) / 8;          // 12500

    // init + degrees + CSR build
    init_kernel<<<nodeBlocks, 256>>>(W0, W1, Wc);
    degree_kernel<<<edgeBlocks, 256>>>(edges);
    finish_deg_bsum_kernel<<<NBLK, 256>>>();
    scan_bsum_kernel<<<1, 512>>>();
    rowstart_kernel<<<NBLK, 256>>>();
    fill_csr_kernel<<<edgeBlocks, 256>>>(edges);

    // layer 0
    gemm_mma_kernel<<<gemmBlocks, 256>>>(x, 0, N_NODES);
    gather_kernel<<<gatherBlocks, 256>>>(b0);

    // layer 1
    gemm_mma_kernel<<<gemmBlocks, 256>>>(nullptr, 1, N_NODES);
    gather_kernel<<<gatherBlocks, 256>>>(b1);

    // classifier (tensor core)
    cls_mma_kernel<<<gemmBlocks, 256>>>(bc, out, N_NODES);
}

// round 13
// speedup vs baseline: 1.0388x; 1.0388x over previous
#include <cuda_runtime.h>
#include <cuda_fp16.h>
#include <cstdint>

#define N_NODES 100000
#define N_EDGES 1600000
#define HID 128
#define NCLS 47
#define NBLK 391                                  // ceil(N_NODES/256)

// ---------------- scratch (static device globals; no runtime allocation) ----
__device__ __half g_yh[(size_t)N_NODES * HID];   // GEMM output fp16 (gather source)
__device__ __half g_hh[(size_t)N_NODES * HID];   // post-activation hidden fp16
__device__ __half g_wt0[HID * HID];              // W0^T fp16  [n][k]
__device__ __half g_wt1[HID * HID];              // W1^T fp16  [n][k]
__device__ __half g_wtc[64 * HID];               // Wc^T fp16  [n][k], rows 47..63 = 0
__device__ float  g_cs[N_NODES];
__device__ float  g_cd[N_NODES];
__device__ int    g_outdeg[N_NODES];
__device__ int    g_indeg [N_NODES];
__device__ int    g_cursor[N_NODES];
__device__ int    g_rowstart[N_NODES];           // segment base per dst (arbitrary order)
__device__ int    g_csrc[N_EDGES];
__device__ int    g_base_cursor;                 // global segment allocator

// ---- fused init: zero counters + W pre-transpose/convert ------------------
__global__ void __launch_bounds__(256) init_kernel(const float* __restrict__ W0,
                                                   const float* __restrict__ W1,
                                                   const float* __restrict__ Wc) {
    int i = blockIdx.x * 256 + threadIdx.x;
    if (i == 0) g_base_cursor = 0;
    if (i < N_NODES) { g_outdeg[i] = 0; g_indeg[i] = 0; g_cursor[i] = 0; }
    if (i < HID * HID) {
        int n = i >> 7, k = i & 127;
        g_wt0[i] = __float2half_rn(W0[k * 128 + n]);
        g_wt1[i] = __float2half_rn(W1[k * 128 + n]);
    }
    if (i < 64 * HID) {
        int n = i >> 7, k = i & 127;
        g_wtc[i] = (n < NCLS) ? __float2half_rn(Wc[k * NCLS + n])
                              : __float2half_rn(0.f);
    }
}

__global__ void degree_kernel(const int* __restrict__ edges) {
    int i = blockIdx.x * blockDim.x + threadIdx.x;
    if (i < N_EDGES) {
        atomicAdd(&g_outdeg[edges[i]], 1);
        atomicAdd(&g_indeg [edges[N_EDGES + i]], 1);
    }
}

// ---- fused: finish degrees + rowstart assignment (one kernel) -------------
// Block-local exclusive scan of indeg; block claims its segment base with a
// single atomicAdd. CSR row segments land in arbitrary order -- gather only
// needs contiguity per dst, so this is sufficient.
__global__ void __launch_bounds__(256) finish_deg_scan_kernel() {
    __shared__ int part[256];
    __shared__ int base_sm;
    int t = threadIdx.x;
    int i = blockIdx.x * 256 + t;
    int v = 0;
    if (i < N_NODES) {
        int od = g_outdeg[i];
        v = g_indeg[i];
        g_cs[i] = rsqrtf(fmaxf((float)od, 1.f));
        g_cd[i] = rsqrtf(fmaxf((float)v,  1.f));
    }
    part[t] = v;
    __syncthreads();
    for (int off = 1; off < 256; off <<= 1) {
        int u = (t >= off) ? part[t - off] : 0;
        __syncthreads();
        part[t] += u;
        __syncthreads();
    }
    if (t == 255) base_sm = atomicAdd(&g_base_cursor, part[255]);
    __syncthreads();
    if (i < N_NODES)
        g_rowstart[i] = base_sm + part[t] - v;   // exclusive within block
}

__global__ void fill_csr_kernel(const int* __restrict__ edges) {
    int i = blockIdx.x * blockDim.x + threadIdx.x;
    if (i < N_EDGES) {
        int s = edges[i];
        int d = edges[N_EDGES + i];
        int pos = g_rowstart[d] + atomicAdd(&g_cursor[d], 1);
        g_csrc[pos] = s;
    }
}

// ---------------- tensor-core GEMM: Yh = fp16((A*c_src) @ W) ---------------
// Block 64x128, two 64-K chunks, software-pipelined. 8 warps (2x4),
// warp tile 32x32, m16n8k16.
__global__ void __launch_bounds__(256) gemm_mma_kernel(
    const float* __restrict__ X, int layer, int M)
{
    __shared__ __align__(16) __half Ah[64][72];
    __shared__ __align__(16) __half Bt[128][72];

    const __half* Wt = layer ? g_wt1 : g_wt0;

    int tid  = threadIdx.x;
    int lane = tid & 31;
    int warp = tid >> 5;
    int wm   = warp >> 2;
    int wn   = warp & 3;
    int g    = lane >> 2;
    int tq   = lane & 3;
    int row0 = blockIdx.x * 64;

    uint32_t ahBase = (uint32_t)__cvta_generic_to_shared(&Ah[0][0]);
    uint32_t btBase = (uint32_t)__cvta_generic_to_shared(&Bt[0][0]);
    int atrow = lane & 15;
    int athalf = (lane >> 4) * 8;
    uint32_t aAddr[2];
#pragma unroll
    for (int ma = 0; ma < 2; ma++)
        aAddr[ma] = ahBase + ((wm * 32 + ma * 16 + atrow) * 72 + athalf) * 2;
    int btrow = (lane & 7) + ((lane >> 4) << 3);
    int bthalf = ((lane >> 3) & 1) * 8;
    uint32_t bAddr[2];
#pragma unroll
    for (int p = 0; p < 2; p++)
        bAddr[p] = btBase + ((wn * 32 + p * 16 + btrow) * 72 + bthalf) * 2;

    int ar[2], akb[2];
#pragma unroll
    for (int t = 0; t < 2; t++) {
        int id = tid + t * 256;
        ar[t]  = id >> 3;
        akb[t] = (id & 7) * 8;
    }
    int bn[4], bkb[4];
#pragma unroll
    for (int t = 0; t < 4; t++) {
        int id = tid + t * 256;
        bn[t]  = id >> 3;
        bkb[t] = (id & 7) * 8;
    }

    float acc[2][4][4];
#pragma unroll
    for (int ma = 0; ma < 2; ma++)
#pragma unroll
        for (int na = 0; na < 4; na++)
#pragma unroll
            for (int q = 0; q < 4; q++) acc[ma][na][q] = 0.f;

    uint4 ast[2], bst[4];

    // ---- load chunk 0 ----
#pragma unroll
    for (int t = 0; t < 2; t++) {
        int grow = row0 + ar[t];
        __half2 h[4];
        if (grow < M) {
            float s = g_cs[grow];
            if (!layer) {
                const float4* p = (const float4*)(X + (size_t)grow * 128 + akb[t]);
                float4 v0 = p[0], v1 = p[1];
                h[0] = __floats2half2_rn(v0.x * s, v0.y * s);
                h[1] = __floats2half2_rn(v0.z * s, v0.w * s);
                h[2] = __floats2half2_rn(v1.x * s, v1.y * s);
                h[3] = __floats2half2_rn(v1.z * s, v1.w * s);
            } else {
                uint4 u = *(const uint4*)(g_hh + (size_t)grow * 128 + akb[t]);
                const __half2* hp = (const __half2*)&u;
#pragma unroll
                for (int q = 0; q < 4; q++) {
                    float2 f = __half22float2(hp[q]);
                    h[q] = __floats2half2_rn(f.x * s, f.y * s);
                }
            }
        } else {
            __half2 z = __floats2half2_rn(0.f, 0.f);
            h[0] = z; h[1] = z; h[2] = z; h[3] = z;
        }
        ast[t].x = *(uint32_t*)&h[0]; ast[t].y = *(uint32_t*)&h[1];
        ast[t].z = *(uint32_t*)&h[2]; ast[t].w = *(uint32_t*)&h[3];
    }
#pragma unroll
    for (int t = 0; t < 4; t++)
        bst[t] = *(const uint4*)(Wt + (size_t)bn[t] * 128 + bkb[t]);

#pragma unroll
    for (int t = 0; t < 2; t++) *(uint4*)&Ah[ar[t]][akb[t]] = ast[t];
#pragma unroll
    for (int t = 0; t < 4; t++) *(uint4*)&Bt[bn[t]][bkb[t]] = bst[t];
    __syncthreads();

    // ---- prefetch chunk 1 into registers ----
#pragma unroll
    for (int t = 0; t < 2; t++) {
        int grow = row0 + ar[t];
        __half2 h[4];
        if (grow < M) {
            float s = g_cs[grow];
            if (!layer) {
                const float4* p = (const float4*)(X + (size_t)grow * 128 + 64 + akb[t]);
                float4 v0 = p[0], v1 = p[1];
                h[0] = __floats2half2_rn(v0.x * s, v0.y * s);
                h[1] = __floats2half2_rn(v0.z * s, v0.w * s);
                h[2] = __floats2half2_rn(v1.x * s, v1.y * s);
                h[3] = __floats2half2_rn(v1.z * s, v1.w * s);
            } else {
                uint4 u = *(const uint4*)(g_hh + (size_t)grow * 128 + 64 + akb[t]);
                const __half2* hp = (const __half2*)&u;
#pragma unroll
                for (int q = 0; q < 4; q++) {
                    float2 f = __half22float2(hp[q]);
                    h[q] = __floats2half2_rn(f.x * s, f.y * s);
                }
            }
        } else {
            __half2 z = __floats2half2_rn(0.f, 0.f);
            h[0] = z; h[1] = z; h[2] = z; h[3] = z;
        }
        ast[t].x = *(uint32_t*)&h[0]; ast[t].y = *(uint32_t*)&h[1];
        ast[t].z = *(uint32_t*)&h[2]; ast[t].w = *(uint32_t*)&h[3];
    }
#pragma unroll
    for (int t = 0; t < 4; t++)
        bst[t] = *(const uint4*)(Wt + (size_t)bn[t] * 128 + 64 + bkb[t]);

    // ---- MMA chunk 0 / store chunk 1 / MMA chunk 1 ----
#pragma unroll
    for (int chunk = 0; chunk < 2; chunk++) {
#pragma unroll
        for (int ks = 0; ks < 64; ks += 16) {
            uint32_t a[2][4], b[4][2];
#pragma unroll
            for (int ma = 0; ma < 2; ma++) {
                asm volatile(
                    "ldmatrix.sync.aligned.m8n8.x4.shared.b16 {%0,%1,%2,%3}, [%4];\n"
                    : "=r"(a[ma][0]), "=r"(a[ma][1]), "=r"(a[ma][2]), "=r"(a[ma][3])
                    : "r"(aAddr[ma] + ks * 2));
            }
#pragma unroll
            for (int p = 0; p < 2; p++) {
                uint32_t r0, r1, r2, r3;
                asm volatile(
                    "ldmatrix.sync.aligned.m8n8.x4.shared.b16 {%0,%1,%2,%3}, [%4];\n"
                    : "=r"(r0), "=r"(r1), "=r"(r2), "=r"(r3)
                    : "r"(bAddr[p] + ks * 2));
                b[p * 2 + 0][0] = r0; b[p * 2 + 0][1] = r1;
                b[p * 2 + 1][0] = r2; b[p * 2 + 1][1] = r3;
            }
#pragma unroll
            for (int ma = 0; ma < 2; ma++)
#pragma unroll
                for (int na = 0; na < 4; na++) {
                    asm volatile(
                        "mma.sync.aligned.m16n8k16.row.col.f32.f16.f16.f32 "
                        "{%0,%1,%2,%3}, {%4,%5,%6,%7}, {%8,%9}, {%0,%1,%2,%3};\n"
                        : "+f"(acc[ma][na][0]), "+f"(acc[ma][na][1]),
                          "+f"(acc[ma][na][2]), "+f"(acc[ma][na][3])
                        : "r"(a[ma][0]), "r"(a[ma][1]), "r"(a[ma][2]), "r"(a[ma][3]),
                          "r"(b[na][0]), "r"(b[na][1]));
                }
        }
        if (chunk == 0) {
            __syncthreads();
#pragma unroll
            for (int t = 0; t < 2; t++) *(uint4*)&Ah[ar[t]][akb[t]] = ast[t];
#pragma unroll
            for (int t = 0; t < 4; t++) *(uint4*)&Bt[bn[t]][bkb[t]] = bst[t];
            __syncthreads();
        }
    }

    // ---- epilogue: fp32 acc -> fp16 g_yh ----
#pragma unroll
    for (int ma = 0; ma < 2; ma++) {
        int r0 = row0 + wm * 32 + ma * 16 + g;
        int r1 = r0 + 8;
#pragma unroll
        for (int na = 0; na < 4; na++) {
            int col = wn * 32 + na * 8 + tq * 2;
            if (r0 < M)
                *(__half2*)(g_yh + (size_t)r0 * 128 + col) =
                    __floats2half2_rn(acc[ma][na][0], acc[ma][na][1]);
            if (r1 < M)
                *(__half2*)(g_yh + (size_t)r1 * 128 + col) =
                    __floats2half2_rn(acc[ma][na][2], acc[ma][na][3]);
        }
    }
}

// ---------------- CSR gather (fp16 src) + scale + bias + relu -> fp16 ------
// round-11 form (measured best): one warp per dst; lane owns 4 features
// (uint2 = 8B). Segment end = beg + indeg (rows in arbitrary order).
__global__ void __launch_bounds__(256) gather_kernel(const float* __restrict__ b) {
    int w    = blockIdx.x * 8 + (threadIdx.x >> 5);
    int lane = threadIdx.x & 31;
    if (w >= N_NODES) return;

    int beg = __ldg(&g_rowstart[w]);
    int end = beg + __ldg(&g_indeg[w]);

    float4 acc = make_float4(0.f, 0.f, 0.f, 0.f);

    for (int base = beg; base < end; base += 32) {
        int n   = end - base;
        int m   = n < 32 ? n : 32;
        int idx = (lane < m) ? __ldg(&g_csrc[base + lane]) : 0;

        int j = 0;
        for (; j + 4 <= m; j += 4) {
            int s0 = __shfl_sync(0xffffffffu, idx, j + 0);
            int s1 = __shfl_sync(0xffffffffu, idx, j + 1);
            int s2 = __shfl_sync(0xffffffffu, idx, j + 2);
            int s3 = __shfl_sync(0xffffffffu, idx, j + 3);
            uint2 r0 = *(const uint2*)(g_yh + (size_t)s0 * 128 + lane * 4);
            uint2 r1 = *(const uint2*)(g_yh + (size_t)s1 * 128 + lane * 4);
            uint2 r2 = *(const uint2*)(g_yh + (size_t)s2 * 128 + lane * 4);
            uint2 r3 = *(const uint2*)(g_yh + (size_t)s3 * 128 + lane * 4);
            float2 a0 = __half22float2(*(const __half2*)&r0.x);
            float2 b0_ = __half22float2(*(const __half2*)&r0.y);
            float2 a1 = __half22float2(*(const __half2*)&r1.x);
            float2 b1_ = __half22float2(*(const __half2*)&r1.y);
            float2 a2 = __half22float2(*(const __half2*)&r2.x);
            float2 b2_ = __half22float2(*(const __half2*)&r2.y);
            float2 a3 = __half22float2(*(const __half2*)&r3.x);
            float2 b3_ = __half22float2(*(const __half2*)&r3.y);
            acc.x += (a0.x + a1.x) + (a2.x + a3.x);
            acc.y += (a0.y + a1.y) + (a2.y + a3.y);
            acc.z += (b0_.x + b1_.x) + (b2_.x + b3_.x);
            acc.w += (b0_.y + b1_.y) + (b2_.y + b3_.y);
        }
        for (; j < m; j++) {
            int s = __shfl_sync(0xffffffffu, idx, j);
            uint2 r = *(const uint2*)(g_yh + (size_t)s * 128 + lane * 4);
            float2 a = __half22float2(*(const __half2*)&r.x);
            float2 c = __half22float2(*(const __half2*)&r.y);
            acc.x += a.x; acc.y += a.y; acc.z += c.x; acc.w += c.y;
        }
    }

    float c = g_cd[w];
    float4 bb = *(const float4*)(b + lane * 4);
    __half2 o0 = __floats2half2_rn(fmaxf(fmaf(acc.x, c, bb.x), 0.f),
                                   fmaxf(fmaf(acc.y, c, bb.y), 0.f));
    __half2 o1 = __floats2half2_rn(fmaxf(fmaf(acc.z, c, bb.z), 0.f),
                                   fmaxf(fmaf(acc.w, c, bb.w), 0.f));
    uint2 pack;
    pack.x = *(uint32_t*)&o0;
    pack.y = *(uint32_t*)&o1;
    *(uint2*)(g_hh + (size_t)w * 128 + lane * 4) = pack;
}

// ---------------- classifier (tensor core): out = g_hh @ Wc + bc -----------
__global__ void __launch_bounds__(256) cls_mma_kernel(
    const float* __restrict__ bc, float* __restrict__ out, int M)
{
    __shared__ __align__(16) __half Ah[64][136];
    __shared__ __align__(16) __half Bt[64][136];

    int tid  = threadIdx.x;
    int lane = tid & 31;
    int warp = tid >> 5;
    int wm   = warp >> 2;
    int wn   = warp & 3;
    int g    = lane >> 2;
    int tq   = lane & 3;
    int row0 = blockIdx.x * 64;

#pragma unroll
    for (int t = 0; t < 4; t++) {
        int id = tid + t * 256;
        int r  = id >> 4;
        int kb = (id & 15) * 8;
        int grow = row0 + r;
        uint4 v = make_uint4(0u, 0u, 0u, 0u);
        if (grow < M) v = *(const uint4*)(g_hh + (size_t)grow * 128 + kb);
        *(uint4*)&Ah[r][kb] = v;
    }
#pragma unroll
    for (int t = 0; t < 4; t++) {
        int id = tid + t * 256;
        int n  = id >> 4;
        int kb = (id & 15) * 8;
        *(uint4*)&Bt[n][kb] = *(const uint4*)(g_wtc + (size_t)n * 128 + kb);
    }
    __syncthreads();

    uint32_t ahBase = (uint32_t)__cvta_generic_to_shared(&Ah[0][0]);
    uint32_t btBase = (uint32_t)__cvta_generic_to_shared(&Bt[0][0]);
    int atrow = lane & 15;
    int athalf = (lane >> 4) * 8;
    uint32_t aAddr[2];
#pragma unroll
    for (int ma = 0; ma < 2; ma++)
        aAddr[ma] = ahBase + ((wm * 32 + ma * 16 + atrow) * 136 + athalf) * 2;
    int btrow = (lane & 7) + ((lane >> 4) << 3);
    int bthalf = ((lane >> 3) & 1) * 8;
    uint32_t bAddr = btBase + ((wn * 16 + btrow) * 136 + bthalf) * 2;

    float acc[2][2][4];
#pragma unroll
    for (int ma = 0; ma < 2; ma++)
#pragma unroll
        for (int na = 0; na < 2; na++)
#pragma unroll
            for (int q = 0; q < 4; q++) acc[ma][na][q] = 0.f;

#pragma unroll
    for (int ks = 0; ks < 128; ks += 16) {
        uint32_t a[2][4], b[2][2];
#pragma unroll
        for (int ma = 0; ma < 2; ma++) {
            asm volatile(
                "ldmatrix.sync.aligned.m8n8.x4.shared.b16 {%0,%1,%2,%3}, [%4];\n"
                : "=r"(a[ma][0]), "=r"(a[ma][1]), "=r"(a[ma][2]), "=r"(a[ma][3])
                : "r"(aAddr[ma] + ks * 2));
        }
        {
            uint32_t r0, r1, r2, r3;
            asm volatile(
                "ldmatrix.sync.aligned.m8n8.x4.shared.b16 {%0,%1,%2,%3}, [%4];\n"
                : "=r"(r0), "=r"(r1), "=r"(r2), "=r"(r3)
                : "r"(bAddr + ks * 2));
            b[0][0] = r0; b[0][1] = r1;
            b[1][0] = r2; b[1][1] = r3;
        }
#pragma unroll
        for (int ma = 0; ma < 2; ma++)
#pragma unroll
            for (int na = 0; na < 2; na++) {
                asm volatile(
                    "mma.sync.aligned.m16n8k16.row.col.f32.f16.f16.f32 "
                    "{%0,%1,%2,%3}, {%4,%5,%6,%7}, {%8,%9}, {%0,%1,%2,%3};\n"
                    : "+f"(acc[ma][na][0]), "+f"(acc[ma][na][1]),
                      "+f"(acc[ma][na][2]), "+f"(acc[ma][na][3])
                    : "r"(a[ma][0]), "r"(a[ma][1]), "r"(a[ma][2]), "r"(a[ma][3]),
                      "r"(b[na][0]), "r"(b[na][1]));
            }
    }

#pragma unroll
    for (int ma = 0; ma < 2; ma++) {
        int r0 = row0 + wm * 32 + ma * 16 + g;
        int r1 = r0 + 8;
#pragma unroll
        for (int na = 0; na < 2; na++) {
            int col = wn * 16 + na * 8 + tq * 2;
            float bb0 = (col < NCLS)     ? bc[col]     : 0.f;
            float bb1 = (col + 1 < NCLS) ? bc[col + 1] : 0.f;
            if (r0 < M) {
                if (col < NCLS)     out[(size_t)r0 * NCLS + col]     = acc[ma][na][0] + bb0;
                if (col + 1 < NCLS) out[(size_t)r0 * NCLS + col + 1] = acc[ma][na][1] + bb1;
            }
            if (r1 < M) {
                if (col < NCLS)     out[(size_t)r1 * NCLS + col]     = acc[ma][na][2] + bb0;
                if (col + 1 < NCLS) out[(size_t)r1 * NCLS + col + 1] = acc[ma][na][3] + bb1;
            }
        }
    }
}

// ---------------- launch ----------------------------------------------------
extern "C" void kernel_launch(void* const* d_in, const int* in_sizes, int n_in,
                              void* d_out, int out_size)
{
    const float* x     = (const float*)d_in[0];
    const int*   edges = (const int*)  d_in[1];
    const float* W0    = (const float*)d_in[2];
    const float* b0    = (const float*)d_in[3];
    const float* W1    = (const float*)d_in[4];
    const float* b1    = (const float*)d_in[5];
    const float* Wc    = (const float*)d_in[6];
    const float* bc    = (const float*)d_in[7];
    float* out = (float*)d_out;

    const int nodeBlocks   = (N_NODES + 255) / 256;      // 391
    const int edgeBlocks   = (N_EDGES + 255) / 256;      // 6250
    const int gemmBlocks   = (N_NODES + 63) / 64;        // 1563
    const int gatherBlocks = (N_NODES + 7) / 8;          // 12500

    // init + degrees + CSR build (scan chain fused to one kernel)
    init_kernel<<<nodeBlocks, 256>>>(W0, W1, Wc);
    degree_kernel<<<edgeBlocks, 256>>>(edges);
    finish_deg_scan_kernel<<<NBLK, 256>>>();
    fill_csr_kernel<<<edgeBlocks, 256>>>(edges);

    // layer 0
    gemm_mma_kernel<<<gemmBlocks, 256>>>(x, 0, N_NODES);
    gather_kernel<<<gatherBlocks, 256>>>(b0);

    // layer 1
    gemm_mma_kernel<<<gemmBlocks, 256>>>(nullptr, 1, N_NODES);
    gather_kernel<<<gatherBlocks, 256>>>(b1);

    // classifier (tensor core)
    cls_mma_kernel<<<gemmBlocks, 256>>>(bc, out, N_NODES);
}

// round 16
// speedup vs baseline: 1.0492x; 1.0101x over previous
#include <cuda_runtime.h>
#include <cuda_fp16.h>
#include <cstdint>

#define N_NODES 100000
#define N_EDGES 1600000
#define HID 128
#define NCLS 47
#define NBLK 391                                  // ceil(N_NODES/256)

// ---------------- scratch (static device globals; no runtime allocation) ----
__device__ __half g_yh[(size_t)N_NODES * HID];   // GEMM output fp16 (gather source)
__device__ __half g_hh[(size_t)N_NODES * HID];   // post-activation hidden fp16
__device__ __half g_wt0[HID * HID];              // W0^T fp16  [n][k]
__device__ __half g_wt1[HID * HID];              // W1^T fp16  [n][k]
__device__ __half g_wtc[64 * HID];               // Wc^T fp16  [n][k], rows 47..63 = 0
__device__ float  g_cs[N_NODES];
__device__ float  g_cd[N_NODES];
__device__ int    g_outdeg[N_NODES];
__device__ int    g_indeg [N_NODES];
__device__ int    g_rowstart[N_NODES];           // segment base per dst (arbitrary order)
__device__ int    g_epos[N_EDGES];               // per-edge position within dst row
__device__ int    g_csrc[N_EDGES];
__device__ int    g_base_cursor;                 // global segment allocator

// ---- fused init: zero counters + W pre-transpose/convert ------------------
__global__ void __launch_bounds__(256) init_kernel(const float* __restrict__ W0,
                                                   const float* __restrict__ W1,
                                                   const float* __restrict__ Wc) {
    int i = blockIdx.x * 256 + threadIdx.x;
    if (i == 0) g_base_cursor = 0;
    if (i < N_NODES) { g_outdeg[i] = 0; g_indeg[i] = 0; }
    if (i < HID * HID) {
        int n = i >> 7, k = i & 127;
        g_wt0[i] = __float2half_rn(W0[k * 128 + n]);
        g_wt1[i] = __float2half_rn(W1[k * 128 + n]);
    }
    if (i < 64 * HID) {
        int n = i >> 7, k = i & 127;
        g_wtc[i] = (n < NCLS) ? __float2half_rn(Wc[k * NCLS + n])
                              : __float2half_rn(0.f);
    }
}

// ---- degrees + per-edge position (atomic return value reused) -------------
__global__ void degree_kernel(const int* __restrict__ edges) {
    int i = blockIdx.x * blockDim.x + threadIdx.x;
    if (i < N_EDGES) {
        atomicAdd(&g_outdeg[edges[i]], 1);
        int p = atomicAdd(&g_indeg[edges[N_EDGES + i]], 1);
        g_epos[i] = p;                            // position within dst row
    }
}

// ---- fused: finish degrees + rowstart assignment (one kernel) -------------
__global__ void __launch_bounds__(256) finish_deg_scan_kernel() {
    __shared__ int part[256];
    __shared__ int base_sm;
    int t = threadIdx.x;
    int i = blockIdx.x * 256 + t;
    int v = 0;
    if (i < N_NODES) {
        int od = g_outdeg[i];
        v = g_indeg[i];
        g_cs[i] = rsqrtf(fmaxf((float)od, 1.f));
        g_cd[i] = rsqrtf(fmaxf((float)v,  1.f));
    }
    part[t] = v;
    __syncthreads();
    for (int off = 1; off < 256; off <<= 1) {
        int u = (t >= off) ? part[t - off] : 0;
        __syncthreads();
        part[t] += u;
        __syncthreads();
    }
    if (t == 255) base_sm = atomicAdd(&g_base_cursor, part[255]);
    __syncthreads();
    if (i < N_NODES)
        g_rowstart[i] = base_sm + part[t] - v;   // exclusive within block
}

// ---- fill CSR: no atomics -- position precomputed in g_epos ---------------
__global__ void fill_csr_kernel(const int* __restrict__ edges) {
    int i = blockIdx.x * blockDim.x + threadIdx.x;
    if (i < N_EDGES) {
        int s = edges[i];
        int d = edges[N_EDGES + i];
        g_csrc[__ldg(&g_rowstart[d]) + g_epos[i]] = s;
    }
}

// ---------------- tensor-core GEMM: Yh = fp16((A*c_src) @ W) ---------------
// Block 64x128, two 64-K chunks, software-pipelined. 8 warps (2x4),
// warp tile 32x32, m16n8k16.
__global__ void __launch_bounds__(256) gemm_mma_kernel(
    const float* __restrict__ X, int layer, int M)
{
    __shared__ __align__(16) __half Ah[64][72];
    __shared__ __align__(16) __half Bt[128][72];

    const __half* Wt = layer ? g_wt1 : g_wt0;

    int tid  = threadIdx.x;
    int lane = tid & 31;
    int warp = tid >> 5;
    int wm   = warp >> 2;
    int wn   = warp & 3;
    int g    = lane >> 2;
    int tq   = lane & 3;
    int row0 = blockIdx.x * 64;

    uint32_t ahBase = (uint32_t)__cvta_generic_to_shared(&Ah[0][0]);
    uint32_t btBase = (uint32_t)__cvta_generic_to_shared(&Bt[0][0]);
    int atrow = lane & 15;
    int athalf = (lane >> 4) * 8;
    uint32_t aAddr[2];
#pragma unroll
    for (int ma = 0; ma < 2; ma++)
        aAddr[ma] = ahBase + ((wm * 32 + ma * 16 + atrow) * 72 + athalf) * 2;
    int btrow = (lane & 7) + ((lane >> 4) << 3);
    int bthalf = ((lane >> 3) & 1) * 8;
    uint32_t bAddr[2];
#pragma unroll
    for (int p = 0; p < 2; p++)
        bAddr[p] = btBase + ((wn * 32 + p * 16 + btrow) * 72 + bthalf) * 2;

    int ar[2], akb[2];
#pragma unroll
    for (int t = 0; t < 2; t++) {
        int id = tid + t * 256;
        ar[t]  = id >> 3;
        akb[t] = (id & 7) * 8;
    }
    int bn[4], bkb[4];
#pragma unroll
    for (int t = 0; t < 4; t++) {
        int id = tid + t * 256;
        bn[t]  = id >> 3;
        bkb[t] = (id & 7) * 8;
    }

    float acc[2][4][4];
#pragma unroll
    for (int ma = 0; ma < 2; ma++)
#pragma unroll
        for (int na = 0; na < 4; na++)
#pragma unroll
            for (int q = 0; q < 4; q++) acc[ma][na][q] = 0.f;

    uint4 ast[2], bst[4];

    // ---- load chunk 0 ----
#pragma unroll
    for (int t = 0; t < 2; t++) {
        int grow = row0 + ar[t];
        __half2 h[4];
        if (grow < M) {
            float s = g_cs[grow];
            if (!layer) {
                const float4* p = (const float4*)(X + (size_t)grow * 128 + akb[t]);
                float4 v0 = p[0], v1 = p[1];
                h[0] = __floats2half2_rn(v0.x * s, v0.y * s);
                h[1] = __floats2half2_rn(v0.z * s, v0.w * s);
                h[2] = __floats2half2_rn(v1.x * s, v1.y * s);
                h[3] = __floats2half2_rn(v1.z * s, v1.w * s);
            } else {
                uint4 u = *(const uint4*)(g_hh + (size_t)grow * 128 + akb[t]);
                const __half2* hp = (const __half2*)&u;
#pragma unroll
                for (int q = 0; q < 4; q++) {
                    float2 f = __half22float2(hp[q]);
                    h[q] = __floats2half2_rn(f.x * s, f.y * s);
                }
            }
        } else {
            __half2 z = __floats2half2_rn(0.f, 0.f);
            h[0] = z; h[1] = z; h[2] = z; h[3] = z;
        }
        ast[t].x = *(uint32_t*)&h[0]; ast[t].y = *(uint32_t*)&h[1];
        ast[t].z = *(uint32_t*)&h[2]; ast[t].w = *(uint32_t*)&h[3];
    }
#pragma unroll
    for (int t = 0; t < 4; t++)
        bst[t] = *(const uint4*)(Wt + (size_t)bn[t] * 128 + bkb[t]);

#pragma unroll
    for (int t = 0; t < 2; t++) *(uint4*)&Ah[ar[t]][akb[t]] = ast[t];
#pragma unroll
    for (int t = 0; t < 4; t++) *(uint4*)&Bt[bn[t]][bkb[t]] = bst[t];
    __syncthreads();

    // ---- prefetch chunk 1 into registers ----
#pragma unroll
    for (int t = 0; t < 2; t++) {
        int grow = row0 + ar[t];
        __half2 h[4];
        if (grow < M) {
            float s = g_cs[grow];
            if (!layer) {
                const float4* p = (const float4*)(X + (size_t)grow * 128 + 64 + akb[t]);
                float4 v0 = p[0], v1 = p[1];
                h[0] = __floats2half2_rn(v0.x * s, v0.y * s);
                h[1] = __floats2half2_rn(v0.z * s, v0.w * s);
                h[2] = __floats2half2_rn(v1.x * s, v1.y * s);
                h[3] = __floats2half2_rn(v1.z * s, v1.w * s);
            } else {
                uint4 u = *(const uint4*)(g_hh + (size_t)grow * 128 + 64 + akb[t]);
                const __half2* hp = (const __half2*)&u;
#pragma unroll
                for (int q = 0; q < 4; q++) {
                    float2 f = __half22float2(hp[q]);
                    h[q] = __floats2half2_rn(f.x * s, f.y * s);
                }
            }
        } else {
            __half2 z = __floats2half2_rn(0.f, 0.f);
            h[0] = z; h[1] = z; h[2] = z; h[3] = z;
        }
        ast[t].x = *(uint32_t*)&h[0]; ast[t].y = *(uint32_t*)&h[1];
        ast[t].z = *(uint32_t*)&h[2]; ast[t].w = *(uint32_t*)&h[3];
    }
#pragma unroll
    for (int t = 0; t < 4; t++)
        bst[t] = *(const uint4*)(Wt + (size_t)bn[t] * 128 + 64 + bkb[t]);

    // ---- MMA chunk 0 / store chunk 1 / MMA chunk 1 ----
#pragma unroll
    for (int chunk = 0; chunk < 2; chunk++) {
#pragma unroll
        for (int ks = 0; ks < 64; ks += 16) {
            uint32_t a[2][4], b[4][2];
#pragma unroll
            for (int ma = 0; ma < 2; ma++) {
                asm volatile(
                    "ldmatrix.sync.aligned.m8n8.x4.shared.b16 {%0,%1,%2,%3}, [%4];\n"
                    : "=r"(a[ma][0]), "=r"(a[ma][1]), "=r"(a[ma][2]), "=r"(a[ma][3])
                    : "r"(aAddr[ma] + ks * 2));
            }
#pragma unroll
            for (int p = 0; p < 2; p++) {
                uint32_t r0, r1, r2, r3;
                asm volatile(
                    "ldmatrix.sync.aligned.m8n8.x4.shared.b16 {%0,%1,%2,%3}, [%4];\n"
                    : "=r"(r0), "=r"(r1), "=r"(r2), "=r"(r3)
                    : "r"(bAddr[p] + ks * 2));
                b[p * 2 + 0][0] = r0; b[p * 2 + 0][1] = r1;
                b[p * 2 + 1][0] = r2; b[p * 2 + 1][1] = r3;
            }
#pragma unroll
            for (int ma = 0; ma < 2; ma++)
#pragma unroll
                for (int na = 0; na < 4; na++) {
                    asm volatile(
                        "mma.sync.aligned.m16n8k16.row.col.f32.f16.f16.f32 "
                        "{%0,%1,%2,%3}, {%4,%5,%6,%7}, {%8,%9}, {%0,%1,%2,%3};\n"
                        : "+f"(acc[ma][na][0]), "+f"(acc[ma][na][1]),
                          "+f"(acc[ma][na][2]), "+f"(acc[ma][na][3])
                        : "r"(a[ma][0]), "r"(a[ma][1]), "r"(a[ma][2]), "r"(a[ma][3]),
                          "r"(b[na][0]), "r"(b[na][1]));
                }
        }
        if (chunk == 0) {
            __syncthreads();
#pragma unroll
            for (int t = 0; t < 2; t++) *(uint4*)&Ah[ar[t]][akb[t]] = ast[t];
#pragma unroll
            for (int t = 0; t < 4; t++) *(uint4*)&Bt[bn[t]][bkb[t]] = bst[t];
            __syncthreads();
        }
    }

    // ---- epilogue: fp32 acc -> fp16 g_yh ----
#pragma unroll
    for (int ma = 0; ma < 2; ma++) {
        int r0 = row0 + wm * 32 + ma * 16 + g;
        int r1 = r0 + 8;
#pragma unroll
        for (int na = 0; na < 4; na++) {
            int col = wn * 32 + na * 8 + tq * 2;
            if (r0 < M)
                *(__half2*)(g_yh + (size_t)r0 * 128 + col) =
                    __floats2half2_rn(acc[ma][na][0], acc[ma][na][1]);
            if (r1 < M)
                *(__half2*)(g_yh + (size_t)r1 * 128 + col) =
                    __floats2half2_rn(acc[ma][na][2], acc[ma][na][3]);
        }
    }
}

// ---------------- CSR gather (fp16 src) + scale + bias + relu -> fp16 ------
// one warp per dst; lane owns 4 features (uint2 = 8B). end = beg + indeg.
__global__ void __launch_bounds__(256) gather_kernel(const float* __restrict__ b) {
    int w    = blockIdx.x * 8 + (threadIdx.x >> 5);
    int lane = threadIdx.x & 31;
    if (w >= N_NODES) return;

    int beg = __ldg(&g_rowstart[w]);
    int end = beg + __ldg(&g_indeg[w]);

    float4 acc = make_float4(0.f, 0.f, 0.f, 0.f);

    for (int base = beg; base < end; base += 32) {
        int n   = end - base;
        int m   = n < 32 ? n : 32;
        int idx = (lane < m) ? __ldg(&g_csrc[base + lane]) : 0;

        int j = 0;
        for (; j + 4 <= m; j += 4) {
            int s0 = __shfl_sync(0xffffffffu, idx, j + 0);
            int s1 = __shfl_sync(0xffffffffu, idx, j + 1);
            int s2 = __shfl_sync(0xffffffffu, idx, j + 2);
            int s3 = __shfl_sync(0xffffffffu, idx, j + 3);
            uint2 r0 = *(const uint2*)(g_yh + (size_t)s0 * 128 + lane * 4);
            uint2 r1 = *(const uint2*)(g_yh + (size_t)s1 * 128 + lane * 4);
            uint2 r2 = *(const uint2*)(g_yh + (size_t)s2 * 128 + lane * 4);
            uint2 r3 = *(const uint2*)(g_yh + (size_t)s3 * 128 + lane * 4);
            float2 a0 = __half22float2(*(const __half2*)&r0.x);
            float2 b0_ = __half22float2(*(const __half2*)&r0.y);
            float2 a1 = __half22float2(*(const __half2*)&r1.x);
            float2 b1_ = __half22float2(*(const __half2*)&r1.y);
            float2 a2 = __half22float2(*(const __half2*)&r2.x);
            float2 b2_ = __half22float2(*(const __half2*)&r2.y);
            float2 a3 = __half22float2(*(const __half2*)&r3.x);
            float2 b3_ = __half22float2(*(const __half2*)&r3.y);
            acc.x += (a0.x + a1.x) + (a2.x + a3.x);
            acc.y += (a0.y + a1.y) + (a2.y + a3.y);
            acc.z += (b0_.x + b1_.x) + (b2_.x + b3_.x);
            acc.w += (b0_.y + b1_.y) + (b2_.y + b3_.y);
        }
        for (; j < m; j++) {
            int s = __shfl_sync(0xffffffffu, idx, j);
            uint2 r = *(const uint2*)(g_yh + (size_t)s * 128 + lane * 4);
            float2 a = __half22float2(*(const __half2*)&r.x);
            float2 c = __half22float2(*(const __half2*)&r.y);
            acc.x += a.x; acc.y += a.y; acc.z += c.x; acc.w += c.y;
        }
    }

    float c = g_cd[w];
    float4 bb = *(const float4*)(b + lane * 4);
    __half2 o0 = __floats2half2_rn(fmaxf(fmaf(acc.x, c, bb.x), 0.f),
                                   fmaxf(fmaf(acc.y, c, bb.y), 0.f));
    __half2 o1 = __floats2half2_rn(fmaxf(fmaf(acc.z, c, bb.z), 0.f),
                                   fmaxf(fmaf(acc.w, c, bb.w), 0.f));
    uint2 pack;
    pack.x = *(uint32_t*)&o0;
    pack.y = *(uint32_t*)&o1;
    *(uint2*)(g_hh + (size_t)w * 128 + lane * 4) = pack;
}

// ---------------- classifier (tensor core): out = g_hh @ Wc + bc -----------
__global__ void __launch_bounds__(256) cls_mma_kernel(
    const float* __restrict__ bc, float* __restrict__ out, int M)
{
    __shared__ __align__(16) __half Ah[64][136];
    __shared__ __align__(16) __half Bt[64][136];

    int tid  = threadIdx.x;
    int lane = tid & 31;
    int warp = tid >> 5;
    int wm   = warp >> 2;
    int wn   = warp & 3;
    int g    = lane >> 2;
    int tq   = lane & 3;
    int row0 = blockIdx.x * 64;

#pragma unroll
    for (int t = 0; t < 4; t++) {
        int id = tid + t * 256;
        int r  = id >> 4;
        int kb = (id & 15) * 8;
        int grow = row0 + r;
        uint4 v = make_uint4(0u, 0u, 0u, 0u);
        if (grow < M) v = *(const uint4*)(g_hh + (size_t)grow * 128 + kb);
        *(uint4*)&Ah[r][kb] = v;
    }
#pragma unroll
    for (int t = 0; t < 4; t++) {
        int id = tid + t * 256;
        int n  = id >> 4;
        int kb = (id & 15) * 8;
        *(uint4*)&Bt[n][kb] = *(const uint4*)(g_wtc + (size_t)n * 128 + kb);
    }
    __syncthreads();

    uint32_t ahBase = (uint32_t)__cvta_generic_to_shared(&Ah[0][0]);
    uint32_t btBase = (uint32_t)__cvta_generic_to_shared(&Bt[0][0]);
    int atrow = lane & 15;
    int athalf = (lane >> 4) * 8;
    uint32_t aAddr[2];
#pragma unroll
    for (int ma = 0; ma < 2; ma++)
        aAddr[ma] = ahBase + ((wm * 32 + ma * 16 + atrow) * 136 + athalf) * 2;
    int btrow = (lane & 7) + ((lane >> 4) << 3);
    int bthalf = ((lane >> 3) & 1) * 8;
    uint32_t bAddr = btBase + ((wn * 16 + btrow) * 136 + bthalf) * 2;

    float acc[2][2][4];
#pragma unroll
    for (int ma = 0; ma < 2; ma++)
#pragma unroll
        for (int na = 0; na < 2; na++)
#pragma unroll
            for (int q = 0; q < 4; q++) acc[ma][na][q] = 0.f;

#pragma unroll
    for (int ks = 0; ks < 128; ks += 16) {
        uint32_t a[2][4], b[2][2];
#pragma unroll
        for (int ma = 0; ma < 2; ma++) {
            asm volatile(
                "ldmatrix.sync.aligned.m8n8.x4.shared.b16 {%0,%1,%2,%3}, [%4];\n"
                : "=r"(a[ma][0]), "=r"(a[ma][1]), "=r"(a[ma][2]), "=r"(a[ma][3])
                : "r"(aAddr[ma] + ks * 2));
        }
        {
            uint32_t r0, r1, r2, r3;
            asm volatile(
                "ldmatrix.sync.aligned.m8n8.x4.shared.b16 {%0,%1,%2,%3}, [%4];\n"
                : "=r"(r0), "=r"(r1), "=r"(r2), "=r"(r3)
                : "r"(bAddr + ks * 2));
            b[0][0] = r0; b[0][1] = r1;
            b[1][0] = r2; b[1][1] = r3;
        }
#pragma unroll
        for (int ma = 0; ma < 2; ma++)
#pragma unroll
            for (int na = 0; na < 2; na++) {
                asm volatile(
                    "mma.sync.aligned.m16n8k16.row.col.f32.f16.f16.f32 "
                    "{%0,%1,%2,%3}, {%4,%5,%6,%7}, {%8,%9}, {%0,%1,%2,%3};\n"
                    : "+f"(acc[ma][na][0]), "+f"(acc[ma][na][1]),
                      "+f"(acc[ma][na][2]), "+f"(acc[ma][na][3])
                    : "r"(a[ma][0]), "r"(a[ma][1]), "r"(a[ma][2]), "r"(a[ma][3]),
                      "r"(b[na][0]), "r"(b[na][1]));
            }
    }

#pragma unroll
    for (int ma = 0; ma < 2; ma++) {
        int r0 = row0 + wm * 32 + ma * 16 + g;
        int r1 = r0 + 8;
#pragma unroll
        for (int na = 0; na < 2; na++) {
            int col = wn * 16 + na * 8 + tq * 2;
            float bb0 = (col < NCLS)     ? bc[col]     : 0.f;
            float bb1 = (col + 1 < NCLS) ? bc[col + 1] : 0.f;
            if (r0 < M) {
                if (col < NCLS)     out[(size_t)r0 * NCLS + col]     = acc[ma][na][0] + bb0;
                if (col + 1 < NCLS) out[(size_t)r0 * NCLS + col + 1] = acc[ma][na][1] + bb1;
            }
            if (r1 < M) {
                if (col < NCLS)     out[(size_t)r1 * NCLS + col]     = acc[ma][na][2] + bb0;
                if (col + 1 < NCLS) out[(size_t)r1 * NCLS + col + 1] = acc[ma][na][3] + bb1;
            }
        }
    }
}

// ---------------- launch ----------------------------------------------------
extern "C" void kernel_launch(void* const* d_in, const int* in_sizes, int n_in,
                              void* d_out, int out_size)
{
    const float* x     = (const float*)d_in[0];
    const int*   edges = (const int*)  d_in[1];
    const float* W0    = (const float*)d_in[2];
    const float* b0    = (const float*)d_in[3];
    const float* W1    = (const float*)d_in[4];
    const float* b1    = (const float*)d_in[5];
    const float* Wc    = (const float*)d_in[6];
    const float* bc    = (const float*)d_in[7];
    float* out = (float*)d_out;

    const int nodeBlocks   = (N_NODES + 255) / 256;      // 391
    const int edgeBlocks   = (N_EDGES + 255) / 256;      // 6250
    const int gemmBlocks   = (N_NODES + 63) / 64;        // 1563
    const int gatherBlocks = (N_NODES + 7) / 8;          // 12500

    // init + degrees + CSR build (fill has no atomics now)
    init_kernel<<<nodeBlocks, 256>>>(W0, W1, Wc);
    degree_kernel<<<edgeBlocks, 256>>>(edges);
    finish_deg_scan_kernel<<<NBLK, 256>>>();
    fill_csr_kernel<<<edgeBlocks, 256>>>(edges);

    // layer 0
    gemm_mma_kernel<<<gemmBlocks, 256>>>(x, 0, N_NODES);
    gather_kernel<<<gatherBlocks, 256>>>(b0);

    // layer 1
    gemm_mma_kernel<<<gemmBlocks, 256>>>(nullptr, 1, N_NODES);
    gather_kernel<<<gatherBlocks, 256>>>(b1);

    // classifier (tensor core)
    cls_mma_kernel<<<gemmBlocks, 256>>>(bc, out, N_NODES);
}

// round 17
// speedup vs baseline: 1.0856x; 1.0347x over previous
#include <cuda_runtime.h>
#include <cuda_fp16.h>
#include <cstdint>

#define N_NODES 100000
#define N_EDGES 1600000
#define HID 128
#define NCLS 47
#define NBLK 391                                  // ceil(N_NODES/256)
#define GEMMB 1563                                // ceil(N_NODES/64)
#define FSTR (GEMMB * 256)                        // fill-role stride = 400128

// ---------------- scratch (static device globals; no runtime allocation) ----
__device__ __half g_yh[(size_t)N_NODES * HID];   // GEMM output fp16 (gather source)
__device__ __half g_hh[(size_t)N_NODES * HID];   // post-activation hidden fp16
__device__ __half g_wt0[HID * HID];              // W0^T fp16  [n][k]
__device__ __half g_wt1[HID * HID];              // W1^T fp16  [n][k]
__device__ __half g_wtc[64 * HID];               // Wc^T fp16  [n][k], rows 47..63 = 0
__device__ float  g_cs[N_NODES];
__device__ float  g_cd[N_NODES];
__device__ int    g_outdeg[N_NODES];
__device__ int    g_indeg [N_NODES];
__device__ int    g_rowstart[N_NODES];           // segment base per dst (arbitrary order)
__device__ int    g_epos[N_EDGES];               // per-edge position within dst row
__device__ int    g_csrc[N_EDGES];
__device__ int    g_base_cursor;                 // global segment allocator

// ---- fused init: zero counters + W pre-transpose/convert ------------------
__global__ void __launch_bounds__(256) init_kernel(const float* __restrict__ W0,
                                                   const float* __restrict__ W1,
                                                   const float* __restrict__ Wc) {
    int i = blockIdx.x * 256 + threadIdx.x;
    if (i == 0) g_base_cursor = 0;
    if (i < N_NODES) { g_outdeg[i] = 0; g_indeg[i] = 0; }
    if (i < HID * HID) {
        int n = i >> 7, k = i & 127;
        g_wt0[i] = __float2half_rn(W0[k * 128 + n]);
        g_wt1[i] = __float2half_rn(W1[k * 128 + n]);
    }
    if (i < 64 * HID) {
        int n = i >> 7, k = i & 127;
        g_wtc[i] = (n < NCLS) ? __float2half_rn(Wc[k * NCLS + n])
                              : __float2half_rn(0.f);
    }
}

// ---- degrees + per-edge position (atomic return value reused) -------------
__global__ void degree_kernel(const int* __restrict__ edges) {
    int i = blockIdx.x * blockDim.x + threadIdx.x;
    if (i < N_EDGES) {
        atomicAdd(&g_outdeg[edges[i]], 1);
        int p = atomicAdd(&g_indeg[edges[N_EDGES + i]], 1);
        g_epos[i] = p;                            // position within dst row
    }
}

// ---- fused: finish degrees + rowstart assignment (one kernel) -------------
__global__ void __launch_bounds__(256) finish_deg_scan_kernel() {
    __shared__ int part[256];
    __shared__ int base_sm;
    int t = threadIdx.x;
    int i = blockIdx.x * 256 + t;
    int v = 0;
    if (i < N_NODES) {
        int od = g_outdeg[i];
        v = g_indeg[i];
        g_cs[i] = rsqrtf(fmaxf((float)od, 1.f));
        g_cd[i] = rsqrtf(fmaxf((float)v,  1.f));
    }
    part[t] = v;
    __syncthreads();
    for (int off = 1; off < 256; off <<= 1) {
        int u = (t >= off) ? part[t - off] : 0;
        __syncthreads();
        part[t] += u;
        __syncthreads();
    }
    if (t == 255) base_sm = atomicAdd(&g_base_cursor, part[255]);
    __syncthreads();
    if (i < N_NODES)
        g_rowstart[i] = base_sm + part[t] - v;   // exclusive within block
}

// ---------------- GEMM body (no cs scaling): Yh = fp16(A @ W) --------------
// Block 64x128, two 64-K chunks, software-pipelined. 8 warps (2x4),
// warp tile 32x32, m16n8k16. layer==0: A = X (fp32->fp16 convert);
// layer==1: A = g_hh (pure fp16 copy).
__device__ __forceinline__ void gemm_body(const float* __restrict__ X,
                                          int layer, int M, int row0) {
    __shared__ __align__(16) __half Ah[64][72];
    __shared__ __align__(16) __half Bt[128][72];

    const __half* Wt = layer ? g_wt1 : g_wt0;

    int tid  = threadIdx.x;
    int lane = tid & 31;
    int warp = tid >> 5;
    int wm   = warp >> 2;
    int wn   = warp & 3;
    int g    = lane >> 2;
    int tq   = lane & 3;

    uint32_t ahBase = (uint32_t)__cvta_generic_to_shared(&Ah[0][0]);
    uint32_t btBase = (uint32_t)__cvta_generic_to_shared(&Bt[0][0]);
    int atrow = lane & 15;
    int athalf = (lane >> 4) * 8;
    uint32_t aAddr[2];
#pragma unroll
    for (int ma = 0; ma < 2; ma++)
        aAddr[ma] = ahBase + ((wm * 32 + ma * 16 + atrow) * 72 + athalf) * 2;
    int btrow = (lane & 7) + ((lane >> 4) << 3);
    int bthalf = ((lane >> 3) & 1) * 8;
    uint32_t bAddr[2];
#pragma unroll
    for (int p = 0; p < 2; p++)
        bAddr[p] = btBase + ((wn * 32 + p * 16 + btrow) * 72 + bthalf) * 2;

    int ar[2], akb[2];
#pragma unroll
    for (int t = 0; t < 2; t++) {
        int id = tid + t * 256;
        ar[t]  = id >> 3;
        akb[t] = (id & 7) * 8;
    }
    int bn[4], bkb[4];
#pragma unroll
    for (int t = 0; t < 4; t++) {
        int id = tid + t * 256;
        bn[t]  = id >> 3;
        bkb[t] = (id & 7) * 8;
    }

    float acc[2][4][4];
#pragma unroll
    for (int ma = 0; ma < 2; ma++)
#pragma unroll
        for (int na = 0; na < 4; na++)
#pragma unroll
            for (int q = 0; q < 4; q++) acc[ma][na][q] = 0.f;

    uint4 ast[2], bst[4];

    // ---- load chunk 0 ----
#pragma unroll
    for (int t = 0; t < 2; t++) {
        int grow = row0 + ar[t];
        if (grow < M) {
            if (!layer) {
                const float4* p = (const float4*)(X + (size_t)grow * 128 + akb[t]);
                float4 v0 = p[0], v1 = p[1];
                __half2 h0 = __floats2half2_rn(v0.x, v0.y);
                __half2 h1 = __floats2half2_rn(v0.z, v0.w);
                __half2 h2 = __floats2half2_rn(v1.x, v1.y);
                __half2 h3 = __floats2half2_rn(v1.z, v1.w);
                ast[t].x = *(uint32_t*)&h0; ast[t].y = *(uint32_t*)&h1;
                ast[t].z = *(uint32_t*)&h2; ast[t].w = *(uint32_t*)&h3;
            } else {
                ast[t] = *(const uint4*)(g_hh + (size_t)grow * 128 + akb[t]);
            }
        } else {
            ast[t] = make_uint4(0u, 0u, 0u, 0u);
        }
    }
#pragma unroll
    for (int t = 0; t < 4; t++)
        bst[t] = *(const uint4*)(Wt + (size_t)bn[t] * 128 + bkb[t]);

#pragma unroll
    for (int t = 0; t < 2; t++) *(uint4*)&Ah[ar[t]][akb[t]] = ast[t];
#pragma unroll
    for (int t = 0; t < 4; t++) *(uint4*)&Bt[bn[t]][bkb[t]] = bst[t];
    __syncthreads();

    // ---- prefetch chunk 1 into registers ----
#pragma unroll
    for (int t = 0; t < 2; t++) {
        int grow = row0 + ar[t];
        if (grow < M) {
            if (!layer) {
                const float4* p = (const float4*)(X + (size_t)grow * 128 + 64 + akb[t]);
                float4 v0 = p[0], v1 = p[1];
                __half2 h0 = __floats2half2_rn(v0.x, v0.y);
                __half2 h1 = __floats2half2_rn(v0.z, v0.w);
                __half2 h2 = __floats2half2_rn(v1.x, v1.y);
                __half2 h3 = __floats2half2_rn(v1.z, v1.w);
                ast[t].x = *(uint32_t*)&h0; ast[t].y = *(uint32_t*)&h1;
                ast[t].z = *(uint32_t*)&h2; ast[t].w = *(uint32_t*)&h3;
            } else {
                ast[t] = *(const uint4*)(g_hh + (size_t)grow * 128 + 64 + akb[t]);
            }
        } else {
            ast[t] = make_uint4(0u, 0u, 0u, 0u);
        }
    }
#pragma unroll
    for (int t = 0; t < 4; t++)
        bst[t] = *(const uint4*)(Wt + (size_t)bn[t] * 128 + 64 + bkb[t]);

    // ---- MMA chunk 0 / store chunk 1 / MMA chunk 1 ----
#pragma unroll
    for (int chunk = 0; chunk < 2; chunk++) {
#pragma unroll
        for (int ks = 0; ks < 64; ks += 16) {
            uint32_t a[2][4], b[4][2];
#pragma unroll
            for (int ma = 0; ma < 2; ma++) {
                asm volatile(
                    "ldmatrix.sync.aligned.m8n8.x4.shared.b16 {%0,%1,%2,%3}, [%4];\n"
                    : "=r"(a[ma][0]), "=r"(a[ma][1]), "=r"(a[ma][2]), "=r"(a[ma][3])
                    : "r"(aAddr[ma] + ks * 2));
            }
#pragma unroll
            for (int p = 0; p < 2; p++) {
                uint32_t r0, r1, r2, r3;
                asm volatile(
                    "ldmatrix.sync.aligned.m8n8.x4.shared.b16 {%0,%1,%2,%3}, [%4];\n"
                    : "=r"(r0), "=r"(r1), "=r"(r2), "=r"(r3)
                    : "r"(bAddr[p] + ks * 2));
                b[p * 2 + 0][0] = r0; b[p * 2 + 0][1] = r1;
                b[p * 2 + 1][0] = r2; b[p * 2 + 1][1] = r3;
            }
#pragma unroll
            for (int ma = 0; ma < 2; ma++)
#pragma unroll
                for (int na = 0; na < 4; na++) {
                    asm volatile(
                        "mma.sync.aligned.m16n8k16.row.col.f32.f16.f16.f32 "
                        "{%0,%1,%2,%3}, {%4,%5,%6,%7}, {%8,%9}, {%0,%1,%2,%3};\n"
                        : "+f"(acc[ma][na][0]), "+f"(acc[ma][na][1]),
                          "+f"(acc[ma][na][2]), "+f"(acc[ma][na][3])
                        : "r"(a[ma][0]), "r"(a[ma][1]), "r"(a[ma][2]), "r"(a[ma][3]),
                          "r"(b[na][0]), "r"(b[na][1]));
                }
        }
        if (chunk == 0) {
            __syncthreads();
#pragma unroll
            for (int t = 0; t < 2; t++) *(uint4*)&Ah[ar[t]][akb[t]] = ast[t];
#pragma unroll
            for (int t = 0; t < 4; t++) *(uint4*)&Bt[bn[t]][bkb[t]] = bst[t];
            __syncthreads();
        }
    }

    // ---- epilogue: fp32 acc -> fp16 g_yh ----
#pragma unroll
    for (int ma = 0; ma < 2; ma++) {
        int r0 = row0 + wm * 32 + ma * 16 + g;
        int r1 = r0 + 8;
#pragma unroll
        for (int na = 0; na < 4; na++) {
            int col = wn * 32 + na * 8 + tq * 2;
            if (r0 < M)
                *(__half2*)(g_yh + (size_t)r0 * 128 + col) =
                    __floats2half2_rn(acc[ma][na][0], acc[ma][na][1]);
            if (r1 < M)
                *(__half2*)(g_yh + (size_t)r1 * 128 + col) =
                    __floats2half2_rn(acc[ma][na][2], acc[ma][na][3]);
        }
    }
}

// ---- fused kernel: parity-interleaved gemm layer-0 + CSR fill -------------
// Even blocks run a gemm tile; odd blocks fill 4 edges/thread (batched MLP).
__global__ void __launch_bounds__(256) gemm0_fill_kernel(
    const float* __restrict__ X, const int* __restrict__ edges, int M)
{
    int role = blockIdx.x & 1;
    int id   = blockIdx.x >> 1;       // 0..GEMMB-1 for both roles

    if (role == 0) {
        gemm_body(X, 0, M, id * 64);
    } else {
        int base = id * 256 + threadIdx.x;
        int s[4], d[4], p[4];
#pragma unroll
        for (int t = 0; t < 4; t++) {
            int e = base + t * FSTR;
            bool ok = e < N_EDGES;
            s[t] = ok ? __ldg(edges + e) : 0;
            d[t] = ok ? __ldg(edges + N_EDGES + e) : 0;
            p[t] = ok ? __ldg(&g_epos[e]) : 0;
        }
#pragma unroll
        for (int t = 0; t < 4; t++) {
            int e = base + t * FSTR;
            if (e < N_EDGES)
                g_csrc[__ldg(&g_rowstart[d[t]]) + p[t]] = s[t];
        }
    }
}

// ---- standalone gemm (layer 1) --------------------------------------------
__global__ void __launch_bounds__(256) gemm_mma_kernel(int M) {
    gemm_body(nullptr, 1, M, blockIdx.x * 64);
}

// ---------------- CSR gather + per-src cs scale + cd/bias/relu -> fp16 -----
// one warp per dst; lane owns 4 features (uint2 = 8B). end = beg + indeg.
// acc += y[src] * cs[src]  (cs via L1-broadcast load after shfl of src id)
__global__ void __launch_bounds__(256) gather_kernel(const float* __restrict__ b) {
    int w    = blockIdx.x * 8 + (threadIdx.x >> 5);
    int lane = threadIdx.x & 31;
    if (w >= N_NODES) return;

    int beg = __ldg(&g_rowstart[w]);
    int end = beg + __ldg(&g_indeg[w]);

    float4 acc = make_float4(0.f, 0.f, 0.f, 0.f);

    for (int base = beg; base < end; base += 32) {
        int n   = end - base;
        int m   = n < 32 ? n : 32;
        int idx = (lane < m) ? __ldg(&g_csrc[base + lane]) : 0;

        int j = 0;
        for (; j + 4 <= m; j += 4) {
            int s0 = __shfl_sync(0xffffffffu, idx, j + 0);
            int s1 = __shfl_sync(0xffffffffu, idx, j + 1);
            int s2 = __shfl_sync(0xffffffffu, idx, j + 2);
            int s3 = __shfl_sync(0xffffffffu, idx, j + 3);
            float c0 = __ldg(&g_cs[s0]);
            float c1 = __ldg(&g_cs[s1]);
            float c2 = __ldg(&g_cs[s2]);
            float c3 = __ldg(&g_cs[s3]);
            uint2 r0 = *(const uint2*)(g_yh + (size_t)s0 * 128 + lane * 4);
            uint2 r1 = *(const uint2*)(g_yh + (size_t)s1 * 128 + lane * 4);
            uint2 r2 = *(const uint2*)(g_yh + (size_t)s2 * 128 + lane * 4);
            uint2 r3 = *(const uint2*)(g_yh + (size_t)s3 * 128 + lane * 4);
            float2 a0 = __half22float2(*(const __half2*)&r0.x);
            float2 b0_ = __half22float2(*(const __half2*)&r0.y);
            float2 a1 = __half22float2(*(const __half2*)&r1.x);
            float2 b1_ = __half22float2(*(const __half2*)&r1.y);
            float2 a2 = __half22float2(*(const __half2*)&r2.x);
            float2 b2_ = __half22float2(*(const __half2*)&r2.y);
            float2 a3 = __half22float2(*(const __half2*)&r3.x);
            float2 b3_ = __half22float2(*(const __half2*)&r3.y);
            acc.x = fmaf(a0.x, c0, fmaf(a1.x, c1, fmaf(a2.x, c2, fmaf(a3.x, c3, acc.x))));
            acc.y = fmaf(a0.y, c0, fmaf(a1.y, c1, fmaf(a2.y, c2, fmaf(a3.y, c3, acc.y))));
            acc.z = fmaf(b0_.x, c0, fmaf(b1_.x, c1, fmaf(b2_.x, c2, fmaf(b3_.x, c3, acc.z))));
            acc.w = fmaf(b0_.y, c0, fmaf(b1_.y, c1, fmaf(b2_.y, c2, fmaf(b3_.y, c3, acc.w))));
        }
        for (; j < m; j++) {
            int s = __shfl_sync(0xffffffffu, idx, j);
            float cf = __ldg(&g_cs[s]);
            uint2 r = *(const uint2*)(g_yh + (size_t)s * 128 + lane * 4);
            float2 a = __half22float2(*(const __half2*)&r.x);
            float2 c = __half22float2(*(const __half2*)&r.y);
            acc.x = fmaf(a.x, cf, acc.x);
            acc.y = fmaf(a.y, cf, acc.y);
            acc.z = fmaf(c.x, cf, acc.z);
            acc.w = fmaf(c.y, cf, acc.w);
        }
    }

    float c = g_cd[w];
    float4 bb = *(const float4*)(b + lane * 4);
    __half2 o0 = __floats2half2_rn(fmaxf(fmaf(acc.x, c, bb.x), 0.f),
                                   fmaxf(fmaf(acc.y, c, bb.y), 0.f));
    __half2 o1 = __floats2half2_rn(fmaxf(fmaf(acc.z, c, bb.z), 0.f),
                                   fmaxf(fmaf(acc.w, c, bb.w), 0.f));
    uint2 pack;
    pack.x = *(uint32_t*)&o0;
    pack.y = *(uint32_t*)&o1;
    *(uint2*)(g_hh + (size_t)w * 128 + lane * 4) = pack;
}

// ---------------- classifier (tensor core): out = g_hh @ Wc + bc -----------
__global__ void __launch_bounds__(256) cls_mma_kernel(
    const float* __restrict__ bc, float* __restrict__ out, int M)
{
    __shared__ __align__(16) __half Ah[64][136];
    __shared__ __align__(16) __half Bt[64][136];

    int tid  = threadIdx.x;
    int lane = tid & 31;
    int warp = tid >> 5;
    int wm   = warp >> 2;
    int wn   = warp & 3;
    int g    = lane >> 2;
    int tq   = lane & 3;
    int row0 = blockIdx.x * 64;

#pragma unroll
    for (int t = 0; t < 4; t++) {
        int id = tid + t * 256;
        int r  = id >> 4;
        int kb = (id & 15) * 8;
        int grow = row0 + r;
        uint4 v = make_uint4(0u, 0u, 0u, 0u);
        if (grow < M) v = *(const uint4*)(g_hh + (size_t)grow * 128 + kb);
        *(uint4*)&Ah[r][kb] = v;
    }
#pragma unroll
    for (int t = 0; t < 4; t++) {
        int id = tid + t * 256;
        int n  = id >> 4;
        int kb = (id & 15) * 8;
        *(uint4*)&Bt[n][kb] = *(const uint4*)(g_wtc + (size_t)n * 128 + kb);
    }
    __syncthreads();

    uint32_t ahBase = (uint32_t)__cvta_generic_to_shared(&Ah[0][0]);
    uint32_t btBase = (uint32_t)__cvta_generic_to_shared(&Bt[0][0]);
    int atrow = lane & 15;
    int athalf = (lane >> 4) * 8;
    uint32_t aAddr[2];
#pragma unroll
    for (int ma = 0; ma < 2; ma++)
        aAddr[ma] = ahBase + ((wm * 32 + ma * 16 + atrow) * 136 + athalf) * 2;
    int btrow = (lane & 7) + ((lane >> 4) << 3);
    int bthalf = ((lane >> 3) & 1) * 8;
    uint32_t bAddr = btBase + ((wn * 16 + btrow) * 136 + bthalf) * 2;

    float acc[2][2][4];
#pragma unroll
    for (int ma = 0; ma < 2; ma++)
#pragma unroll
        for (int na = 0; na < 2; na++)
#pragma unroll
            for (int q = 0; q < 4; q++) acc[ma][na][q] = 0.f;

#pragma unroll
    for (int ks = 0; ks < 128; ks += 16) {
        uint32_t a[2][4], b[2][2];
#pragma unroll
        for (int ma = 0; ma < 2; ma++) {
            asm volatile(
                "ldmatrix.sync.aligned.m8n8.x4.shared.b16 {%0,%1,%2,%3}, [%4];\n"
                : "=r"(a[ma][0]), "=r"(a[ma][1]), "=r"(a[ma][2]), "=r"(a[ma][3])
                : "r"(aAddr[ma] + ks * 2));
        }
        {
            uint32_t r0, r1, r2, r3;
            asm volatile(
                "ldmatrix.sync.aligned.m8n8.x4.shared.b16 {%0,%1,%2,%3}, [%4];\n"
                : "=r"(r0), "=r"(r1), "=r"(r2), "=r"(r3)
                : "r"(bAddr + ks * 2));
            b[0][0] = r0; b[0][1] = r1;
            b[1][0] = r2; b[1][1] = r3;
        }
#pragma unroll
        for (int ma = 0; ma < 2; ma++)
#pragma unroll
            for (int na = 0; na < 2; na++) {
                asm volatile(
                    "mma.sync.aligned.m16n8k16.row.col.f32.f16.f16.f32 "
                    "{%0,%1,%2,%3}, {%4,%5,%6,%7}, {%8,%9}, {%0,%1,%2,%3};\n"
                    : "+f"(acc[ma][na][0]), "+f"(acc[ma][na][1]),
                      "+f"(acc[ma][na][2]), "+f"(acc[ma][na][3])
                    : "r"(a[ma][0]), "r"(a[ma][1]), "r"(a[ma][2]), "r"(a[ma][3]),
                      "r"(b[na][0]), "r"(b[na][1]));
            }
    }

#pragma unroll
    for (int ma = 0; ma < 2; ma++) {
        int r0 = row0 + wm * 32 + ma * 16 + g;
        int r1 = r0 + 8;
#pragma unroll
        for (int na = 0; na < 2; na++) {
            int col = wn * 16 + na * 8 + tq * 2;
            float bb0 = (col < NCLS)     ? bc[col]     : 0.f;
            float bb1 = (col + 1 < NCLS) ? bc[col + 1] : 0.f;
            if (r0 < M) {
                if (col < NCLS)     out[(size_t)r0 * NCLS + col]     = acc[ma][na][0] + bb0;
                if (col + 1 < NCLS) out[(size_t)r0 * NCLS + col + 1] = acc[ma][na][1] + bb1;
            }
            if (r1 < M) {
                if (col < NCLS)     out[(size_t)r1 * NCLS + col]     = acc[ma][na][2] + bb0;
                if (col + 1 < NCLS) out[(size_t)r1 * NCLS + col + 1] = acc[ma][na][3] + bb1;
            }
        }
    }
}

// ---------------- launch ----------------------------------------------------
extern "C" void kernel_launch(void* const* d_in, const int* in_sizes, int n_in,
                              void* d_out, int out_size)
{
    const float* x     = (const float*)d_in[0];
    const int*   edges = (const int*)  d_in[1];
    const float* W0    = (const float*)d_in[2];
    const float* b0    = (const float*)d_in[3];
    const float* W1    = (const float*)d_in[4];
    const float* b1    = (const float*)d_in[5];
    const float* Wc    = (const float*)d_in[6];
    const float* bc    = (const float*)d_in[7];
    float* out = (float*)d_out;

    const int nodeBlocks   = (N_NODES + 255) / 256;      // 391
    const int edgeBlocks   = (N_EDGES + 255) / 256;      // 6250
    const int gatherBlocks = (N_NODES + 7) / 8;          // 12500

    // init + degrees + scan
    init_kernel<<<nodeBlocks, 256>>>(W0, W1, Wc);
    degree_kernel<<<edgeBlocks, 256>>>(edges);
    finish_deg_scan_kernel<<<NBLK, 256>>>();

    // layer-0 GEMM fused (parity-interleaved) with CSR fill
    gemm0_fill_kernel<<<2 * GEMMB, 256>>>(x, edges, N_NODES);
    gather_kernel<<<gatherBlocks, 256>>>(b0);

    // layer 1
    gemm_mma_kernel<<<GEMMB, 256>>>(N_NODES);
    gather_kernel<<<gatherBlocks, 256>>>(b1);

    // classifier (tensor core)
    cls_mma_kernel<<<GEMMB, 256>>>(bc, out, N_NODES);
}